// round 14
// baseline (speedup 1.0000x reference)
#include <cuda_runtime.h>
#include <cstdint>

// HeteroEmbedding: out[n] = tables[types[n], x[n]]  (row 0 of each table is zero,
// so the padding mask is implicit in the gather).
//
// Inputs: d_in[0] x int32[N], d_in[1] types int32[N], d_in[2] tables f32[8,50000,128]
// Output: f32[N,128]
//
// HBM-bound gather. 8 rows per warp:
//   - 256-bit LDG.256 loads with L2::evict_last (sm_103 requires v8.b32 for this
//     policy): half-warp per row, one instruction = 2 rows (1KB), 4 independent
//     loads = 4KB in flight per warp.
//   - output via evict-first __stcs so the 1GB write stream yields L2 to the table.

#define VOCAB 50000
#define ROW_BYTES 512           // 128 f32

struct U8 { unsigned u0,u1,u2,u3,u4,u5,u6,u7; };

__device__ __forceinline__ U8 ld256_evict_last(const void* p)
{
    U8 v;
    asm("ld.global.nc.L2::evict_last.v8.b32 {%0,%1,%2,%3,%4,%5,%6,%7}, [%8];"
        : "=r"(v.u0), "=r"(v.u1), "=r"(v.u2), "=r"(v.u3),
          "=r"(v.u4), "=r"(v.u5), "=r"(v.u6), "=r"(v.u7)
        : "l"(p));
    return v;
}

__global__ void __launch_bounds__(256)
hetero_embed_kernel(const int* __restrict__ x,
                    const int* __restrict__ types,
                    const char* __restrict__ tables,
                    char* __restrict__ out,
                    int n)
{
    long long warp = (long long)((blockIdx.x * (unsigned)blockDim.x + threadIdx.x) >> 5);
    int lane = threadIdx.x & 31;
    long long base = warp * 8;
    if (base >= n) return;

    int sub = lane >> 4;        // which of the 2 rows this half-warp handles
    int off = (lane & 15) * 32; // byte offset within the 512B row

    if (base + 7 < n) {
        // broadcast index loads (2 sectors each)
        int4 xa = __ldg((const int4*)(x + base));
        int4 xb = __ldg((const int4*)(x + base + 4));
        int4 ta = __ldg((const int4*)(types + base));
        int4 tb = __ldg((const int4*)(types + base + 4));

        // per-half-warp row selection, explicit selects (no local-mem arrays)
        int x0 = sub ? xa.y : xa.x;   int t0 = sub ? ta.y : ta.x;   // rows base+0/1
        int x1 = sub ? xa.w : xa.z;   int t1 = sub ? ta.w : ta.z;   // rows base+2/3
        int x2 = sub ? xb.y : xb.x;   int t2 = sub ? tb.y : tb.x;   // rows base+4/5
        int x3 = sub ? xb.w : xb.z;   int t3 = sub ? tb.w : tb.z;   // rows base+6/7

        const char* p0 = tables + ((size_t)t0 * VOCAB + (size_t)x0) * ROW_BYTES + off;
        const char* p1 = tables + ((size_t)t1 * VOCAB + (size_t)x1) * ROW_BYTES + off;
        const char* p2 = tables + ((size_t)t2 * VOCAB + (size_t)x2) * ROW_BYTES + off;
        const char* p3 = tables + ((size_t)t3 * VOCAB + (size_t)x3) * ROW_BYTES + off;

        // 4 independent 1KB gathers in flight (MLP=4, 4KB/warp)
        U8 v0 = ld256_evict_last(p0);
        U8 v1 = ld256_evict_last(p1);
        U8 v2 = ld256_evict_last(p2);
        U8 v3 = ld256_evict_last(p3);

        // 4KB contiguous evict-first store burst
        char* o = out + (size_t)base * ROW_BYTES + (size_t)sub * ROW_BYTES + off;
        __stcs((float4*)(o + 0 * 2 * ROW_BYTES),      *(const float4*)&v0.u0);
        __stcs((float4*)(o + 0 * 2 * ROW_BYTES + 16), *(const float4*)&v0.u4);
        __stcs((float4*)(o + 1 * 2 * ROW_BYTES),      *(const float4*)&v1.u0);
        __stcs((float4*)(o + 1 * 2 * ROW_BYTES + 16), *(const float4*)&v1.u4);
        __stcs((float4*)(o + 2 * 2 * ROW_BYTES),      *(const float4*)&v2.u0);
        __stcs((float4*)(o + 2 * 2 * ROW_BYTES + 16), *(const float4*)&v2.u4);
        __stcs((float4*)(o + 3 * 2 * ROW_BYTES),      *(const float4*)&v3.u0);
        __stcs((float4*)(o + 3 * 2 * ROW_BYTES + 16), *(const float4*)&v3.u4);
    } else {
        // scalar tail: plain float4 path, all 32 lanes on one row
        int l16 = (lane & 15);
        for (long long r = base + sub; r < n; r += 2) {
            int xi = __ldg(&x[r]);
            int ti = __ldg(&types[r]);
            const float4* src = (const float4*)(tables + ((size_t)ti * VOCAB + (size_t)xi) * ROW_BYTES);
            float4* dst = (float4*)(out + (size_t)r * ROW_BYTES);
            float4 a = __ldg(src + l16);
            float4 b = __ldg(src + 16 + l16);
            __stcs(dst + l16, a);
            __stcs(dst + 16 + l16, b);
        }
    }
}

extern "C" void kernel_launch(void* const* d_in, const int* in_sizes, int n_in,
                              void* d_out, int out_size)
{
    const int*  x      = (const int*)d_in[0];
    const int*  types  = (const int*)d_in[1];
    const char* tables = (const char*)d_in[2];
    char*       out    = (char*)d_out;

    int n = in_sizes[0];                               // N rows
    long long warps = ((long long)n + 7) / 8;          // 8 rows per warp
    long long total_threads = warps * 32;
    int block = 256;
    int grid = (int)((total_threads + block - 1) / block);

    hetero_embed_kernel<<<grid, block>>>(x, types, tables, out, n);
}

// round 15
// speedup vs baseline: 1.0245x; 1.0245x over previous
#include <cuda_runtime.h>
#include <cstdint>

// HeteroEmbedding: out[n] = tables[types[n], x[n]]  (row 0 of each table is zero,
// so the padding mask is implicit in the gather).
//
// Inputs: d_in[0] x int32[N], d_in[1] types int32[N], d_in[2] tables f32[8,50000,128]
// Output: f32[N,128]
//
// HBM-bound gather at fixed ~1.79GB DRAM traffic (R13 showed L2 policy can't cut
// the read stream). Sole lever: DRAM utilization. 8 rows per warp, full warp per
// 512B row (float4/lane — the low-L1-pressure pattern from R11), 8 independent
// gathers in flight (4KB/warp), evict-first stores.

#define VOCAB 50000
#define EMBED 128
#define F4_PER_ROW (EMBED / 4)   // 32 float4 per row: 1 float4 per lane

__global__ void __launch_bounds__(256)
hetero_embed_kernel(const int* __restrict__ x,
                    const int* __restrict__ types,
                    const float4* __restrict__ tables,
                    float4* __restrict__ out,
                    int n)
{
    long long warp = (long long)((blockIdx.x * (unsigned)blockDim.x + threadIdx.x) >> 5);
    int lane = threadIdx.x & 31;
    long long base = warp * 8;
    if (base >= n) return;

    if (base + 7 < n) {
        // broadcast index loads (all lanes same address -> 1-2 sectors each)
        int4 xa = __ldg((const int4*)(x + base));
        int4 xb = __ldg((const int4*)(x + base + 4));
        int4 ta = __ldg((const int4*)(types + base));
        int4 tb = __ldg((const int4*)(types + base + 4));

        size_t r0 = ((size_t)ta.x * VOCAB + (size_t)xa.x) * F4_PER_ROW + lane;
        size_t r1 = ((size_t)ta.y * VOCAB + (size_t)xa.y) * F4_PER_ROW + lane;
        size_t r2 = ((size_t)ta.z * VOCAB + (size_t)xa.z) * F4_PER_ROW + lane;
        size_t r3 = ((size_t)ta.w * VOCAB + (size_t)xa.w) * F4_PER_ROW + lane;
        size_t r4 = ((size_t)tb.x * VOCAB + (size_t)xb.x) * F4_PER_ROW + lane;
        size_t r5 = ((size_t)tb.y * VOCAB + (size_t)xb.y) * F4_PER_ROW + lane;
        size_t r6 = ((size_t)tb.z * VOCAB + (size_t)xb.z) * F4_PER_ROW + lane;
        size_t r7 = ((size_t)tb.w * VOCAB + (size_t)xb.w) * F4_PER_ROW + lane;

        // 8 independent 512B row gathers in flight (4KB/warp)
        float4 v0 = __ldg(&tables[r0]);
        float4 v1 = __ldg(&tables[r1]);
        float4 v2 = __ldg(&tables[r2]);
        float4 v3 = __ldg(&tables[r3]);
        float4 v4 = __ldg(&tables[r4]);
        float4 v5 = __ldg(&tables[r5]);
        float4 v6 = __ldg(&tables[r6]);
        float4 v7 = __ldg(&tables[r7]);

        // 4KB contiguous evict-first store burst
        float4* o = out + (size_t)base * F4_PER_ROW + lane;
        __stcs(o + 0 * F4_PER_ROW, v0);
        __stcs(o + 1 * F4_PER_ROW, v1);
        __stcs(o + 2 * F4_PER_ROW, v2);
        __stcs(o + 3 * F4_PER_ROW, v3);
        __stcs(o + 4 * F4_PER_ROW, v4);
        __stcs(o + 5 * F4_PER_ROW, v5);
        __stcs(o + 6 * F4_PER_ROW, v6);
        __stcs(o + 7 * F4_PER_ROW, v7);
    } else {
        // scalar tail (N % 8 != 0 safety)
        for (long long r = base; r < n; r++) {
            int xi = __ldg(&x[r]);
            int ti = __ldg(&types[r]);
            size_t rf = ((size_t)ti * VOCAB + (size_t)xi) * F4_PER_ROW + lane;
            float4 v = __ldg(&tables[rf]);
            __stcs(&out[(size_t)r * F4_PER_ROW + lane], v);
        }
    }
}

extern "C" void kernel_launch(void* const* d_in, const int* in_sizes, int n_in,
                              void* d_out, int out_size)
{
    const int*    x      = (const int*)d_in[0];
    const int*    types  = (const int*)d_in[1];
    const float4* tables = (const float4*)d_in[2];
    float4*       out    = (float4*)d_out;

    int n = in_sizes[0];                               // N rows
    long long warps = ((long long)n + 7) / 8;          // 8 rows per warp
    long long total_threads = warps * 32;
    int block = 256;
    int grid = (int)((total_threads + block - 1) / block);

    hetero_embed_kernel<<<grid, block>>>(x, types, tables, out, n);
}